// round 14
// baseline (speedup 1.0000x reference)
#include <cuda_runtime.h>
#include <cuda_bf16.h>
#include <cstdint>

// Algebraic collapse (alpha=1): exp(lse) = sum_r exp(ln(x_r+1)+k_r+5) = sum_r (x_r+1)e^{k_r+5}
// -> out[m,co] = sum_r A[m,r]*W''[r,co] + C[co],  W'' = e^{k+5}-dw,
//    C = sum_r e^{k_r+5} - dx*sum_r k_r + bias.
// GEMM M=6272(=98x64), N=64, K=288(=18 k16 steps) via mma.sync.m16n8k16 bf16.
// R14: SINGLE fused kernel. Block 98 = weight producer (W'' bf16 + C) ->
// release flag; blocks 0..97 stage their A tile straight from fp32 x (inline
// bf16 convert, block-local, no cross-block dep), acquire-spin on the flag
// only before loading B. Flag/counter self-reset each launch (graph-safe).

#define B_   8
#define H_   28
#define W_   28

__device__ uint4    g_w4[64 * 40];    // bf16 [64][320] = W''^T, cols 288..319 = 0
__device__ float    g_C[64];
__device__ unsigned g_flag = 0;       // 0 -> weights not ready, 1 -> ready
__device__ unsigned g_consumed = 0;   // consumer count for per-launch reset

__device__ __forceinline__ uint32_t smem_u32(const void* p) {
    uint32_t a;
    asm("{ .reg .u64 t; cvta.to.shared.u64 t, %1; cvt.u32.u64 %0, t; }" : "=r"(a) : "l"(p));
    return a;
}
__device__ __forceinline__ unsigned ld_acq(const unsigned* p) {
    unsigned v;
    asm volatile("ld.acquire.gpu.global.b32 %0, [%1];" : "=r"(v) : "l"(p) : "memory");
    return v;
}
__device__ __forceinline__ void cpasync16(uint32_t dst, const void* src) {
    asm volatile("{ .reg .u64 g; cvta.to.global.u64 g, %1; "
                 "cp.async.ca.shared.global [%0], [g], 16; }"
                 :: "r"(dst), "l"(src) : "memory");
}
__device__ __forceinline__ void cpasync_wait() {
    asm volatile("cp.async.commit_group;\n\tcp.async.wait_group 0;" ::: "memory");
}
__device__ __forceinline__ void ldmx4(uint32_t* r, uint32_t addr) {
    asm volatile("ldmatrix.sync.aligned.m8n8.x4.shared.b16 {%0,%1,%2,%3}, [%4];"
                 : "=r"(r[0]), "=r"(r[1]), "=r"(r[2]), "=r"(r[3]) : "r"(addr));
}
__device__ __forceinline__ void mma16816(float* d, const uint32_t* a,
                                         uint32_t b0, uint32_t b1) {
    asm volatile(
        "mma.sync.aligned.m16n8k16.row.col.f32.bf16.bf16.f32 "
        "{%0,%1,%2,%3}, {%4,%5,%6,%7}, {%8,%9}, {%0,%1,%2,%3};"
        : "+f"(d[0]), "+f"(d[1]), "+f"(d[2]), "+f"(d[3])
        : "r"(a[0]), "r"(a[1]), "r"(a[2]), "r"(a[3]), "r"(b0), "r"(b1));
}
__device__ __forceinline__ uint32_t pack_bf16x2(float a, float b) {
    __nv_bfloat162 t = __floats2bfloat162_rn(a, b);
    return *reinterpret_cast<uint32_t*>(&t);
}

constexpr int STRB  = 592;                 // 37*16B rows: conflict-free ldmatrix
constexpr int OFF_A = 0;                   // 64*592 = 37888 ; sD aliases this later
constexpr int OFF_B = 37888;               // 64*592 = 37888
constexpr int OFF_C = 75776;               // 64 floats
constexpr int SMEMB = OFF_C + 256;
constexpr int CNT   = 512;                 // 16 warps

__global__ void __launch_bounds__(CNT) fused_kernel(
    const float* __restrict__ x, const float* __restrict__ k,
    const float* __restrict__ bias,
    const float* __restrict__ dxp, const float* __restrict__ dwp,
    float* __restrict__ out)
{
    extern __shared__ __align__(16) char sm[];
    const uint32_t smb = smem_u32(sm);
    const int tid = threadIdx.x;

    // =================== producer block: weights + C ===================
    if (blockIdx.x == 98) {
        float* se = reinterpret_cast<float*>(sm);          // [512]
        float* sk = reinterpret_cast<float*>(sm) + 512;
        __nv_bfloat16* w2 = reinterpret_cast<__nv_bfloat16*>(g_w4);
        const int co = tid & 63;
        const int r8 = tid >> 6;            // 0..7
        const float dw = dwp[0];
        float pse = 0.f, psk = 0.f;
        #pragma unroll
        for (int rr = r8; rr < 288; rr += 8) {
            float kv = k[rr * 64 + co];
            float e  = __expf(kv + 5.0f);
            w2[co * 320 + rr] = __float2bfloat16(e - dw);
            pse += e; psk += kv;
        }
        // zero-pad K columns 288..319
        #pragma unroll
        for (int rr = 288 + r8; rr < 320; rr += 8)
            w2[co * 320 + rr] = __float2bfloat16(0.f);
        se[tid] = pse; sk[tid] = psk;
        __syncthreads();
        if (tid < 64) {
            float SE = 0.f, SK = 0.f;
            #pragma unroll
            for (int j = 0; j < 8; j++) { SE += se[j * 64 + tid]; SK += sk[j * 64 + tid]; }
            g_C[tid] = SE - dxp[0] * SK + bias[tid];
        }
        __syncthreads();
        __threadfence();
        if (tid == 0) atomicExch(&g_flag, 1u);   // release (fence + store)
        return;
    }

    // =================== consumer blocks: implicit-GEMM conv ===================
    const int wid  = tid >> 5;
    const int lane = tid & 31;
    const int t    = blockIdx.x;             // M-tile, 98 tiles of 64 rows

    // ---- stage A locally from fp32 x (inline bf16 convert) ----
    {
        const int row   = tid >> 3;          // 0..63
        const int lane8 = tid & 7;
        int m = t * 64 + row;
        int b = m / 784, rem = m - b * 784;
        int h = rem / 28, w = rem - h * 28;
        const float* xb = x + (size_t)b * 32 * 784;
        char* dA = sm + OFF_A + row * STRB;
        #pragma unroll
        for (int i = 0; i < 5; i++) {
            int c36 = lane8 + 8 * i;
            if (c36 < 36) {
                int seg = c36 >> 2, c8 = c36 & 3;          // 8 cins per 16B chunk
                int kh = seg / 3, kw = seg - kh * 3;
                int ir = h + kh - 1, ic = w + kw - 1;
                uint4 v = make_uint4(0, 0, 0, 0);
                if ((unsigned)ir < 28u && (unsigned)ic < 28u) {
                    const float* p = xb + (size_t)(c8 * 8) * 784 + ir * 28 + ic;
                    v.x = pack_bf16x2(p[0 * 784], p[1 * 784]);
                    v.y = pack_bf16x2(p[2 * 784], p[3 * 784]);
                    v.z = pack_bf16x2(p[4 * 784], p[5 * 784]);
                    v.w = pack_bf16x2(p[6 * 784], p[7 * 784]);
                }
                *reinterpret_cast<uint4*>(dA + c36 * 16) = v;
            }
        }
    }

    // ---- acquire weights flag (overlapped with A staging above) ----
    if (tid == 0) {
        while (ld_acq(&g_flag) == 0) { }
        unsigned c = atomicAdd(&g_consumed, 1u);
        if (c == 97u) {                       // last consumer resets for next launch
            atomicExch(&g_consumed, 0u);
            atomicExch(&g_flag, 0u);
        }
    }
    __syncthreads();

    // ---- stage B (W''^T) via cp.async; C into smem ----
    float* sC = reinterpret_cast<float*>(sm + OFF_C);
    if (tid < 64) sC[tid] = g_C[tid];
    {
        const int row   = tid >> 3;
        const int lane8 = tid & 7;
        uint32_t dB = smb + OFF_B + row * STRB;
        const uint4* wrow = &g_w4[row * 40];
        #pragma unroll
        for (int i = 0; i < 5; i++) {
            int c = lane8 + 8 * i;
            if (c < 36) cpasync16(dB + c * 16, wrow + c);
        }
    }
    cpasync_wait();
    __syncthreads();

    // ---- 16 warps = 4(M) x 4(N); warp tile 16M x 16N; 2 K-chains ----
    const int wm = (wid & 3) * 16;
    const int wn = (wid >> 2) * 16;
    uint32_t aAddr = smb + OFF_A + (uint32_t)(wm + (lane & 15)) * STRB + (lane >> 4) * 16;
    uint32_t bAddr = smb + OFF_B + (uint32_t)(wn + (lane & 15)) * STRB + (lane >> 4) * 16;

    float acc0[8], acc1[8];
    #pragma unroll
    for (int i = 0; i < 8; i++) { acc0[i] = 0.f; acc1[i] = 0.f; }

    #pragma unroll
    for (int ks = 0; ks < 9; ks++) {
        uint32_t a0[4], b0[4], a1[4], b1[4];
        ldmx4(a0, aAddr + ks * 32);
        ldmx4(b0, bAddr + ks * 32);
        ldmx4(a1, aAddr + (ks + 9) * 32);
        ldmx4(b1, bAddr + (ks + 9) * 32);
        mma16816(acc0 + 0, a0, b0[0], b0[2]);
        mma16816(acc0 + 4, a0, b0[1], b0[3]);
        mma16816(acc1 + 0, a1, b1[0], b1[2]);
        mma16816(acc1 + 4, a1, b1[1], b1[3]);
    }
    #pragma unroll
    for (int i = 0; i < 8; i++) acc0[i] += acc1[i];

    // ---- epilogue: frags -> smem [co][j] (aliases A), coalesced STG ----
    __syncthreads();
    float* sD = reinterpret_cast<float*>(sm + OFF_A);   // stride 65
    {
        const int row  = lane >> 2;
        const int colp = (lane & 3) * 2;
        int j0 = wm + row, j1 = j0 + 8;
        #pragma unroll
        for (int jj = 0; jj < 2; jj++) {
            int co = wn + jj * 8 + colp;
            sD[(co    ) * 65 + j0] = acc0[jj * 4 + 0];
            sD[(co + 1) * 65 + j0] = acc0[jj * 4 + 1];
            sD[(co    ) * 65 + j1] = acc0[jj * 4 + 2];
            sD[(co + 1) * 65 + j1] = acc0[jj * 4 + 3];
        }
    }
    __syncthreads();
    {
        int m0 = t * 64;
        int b0 = m0 / 784;
        int jb = (b0 + 1) * 784 - m0;        // j >= jb -> next batch image
        #pragma unroll
        for (int i = 0; i < 8; i++) {
            int idx = i * CNT + tid;
            int co  = idx >> 6;
            int j   = idx & 63;
            int b   = b0 + (j >= jb ? 1 : 0);
            int hw  = m0 + j - b * 784;
            out[((size_t)(b * 64 + co)) * 784 + hw] = sD[co * 65 + j] + sC[co];
        }
    }
}

// ---------------- launch ----------------
extern "C" void kernel_launch(void* const* d_in, const int* in_sizes, int n_in,
                              void* d_out, int out_size)
{
    (void)in_sizes; (void)n_in; (void)out_size;
    const float* x    = (const float*)d_in[0];
    const float* k    = (const float*)d_in[1];
    const float* bias = (const float*)d_in[2];
    const float* dx   = (const float*)d_in[3];
    const float* dw   = (const float*)d_in[4];
    float* out        = (float*)d_out;

    cudaFuncSetAttribute(fused_kernel,
                         cudaFuncAttributeMaxDynamicSharedMemorySize, SMEMB);

    // 99 blocks: 0..97 conv tiles, 98 weight producer. All co-resident on 148
    // SMs -> the acquire spin cannot deadlock.
    fused_kernel<<<99, CNT, SMEMB>>>(x, k, bias, dx, dw, out);
}

// round 15
// speedup vs baseline: 3.2955x; 3.2955x over previous
#include <cuda_runtime.h>
#include <cuda_bf16.h>
#include <cstdint>

// Algebraic collapse (alpha=1): exp(lse) = sum_r exp(ln(x_r+1)+k_r+5) = sum_r (x_r+1)e^{k_r+5}
// -> out[m,co] = sum_r A[m,r]*W''[r,co] + C[co],  W'' = e^{k+5}-dw,
//    C = sum_r e^{k_r+5} - dx*sum_r k_r + bias.
// GEMM M=6272(=98x64), N=64, K=288(=18 k16 steps) via mma.sync.m16n8k16 bf16.
// R15: prep = weights-only (A staged in-conv from fp32 x, as validated in R14);
// conv launched with Programmatic Dependent Launch so its prologue (ramp +
// A-staging) overlaps prep; griddepcontrol.wait guards the g_w4/g_C reads.

#define B_   8

__device__ uint4 g_w4[64 * 40];    // bf16 [64][320] = W''^T, cols 288..319 = 0
__device__ float g_C[64];

__device__ __forceinline__ uint32_t smem_u32(const void* p) {
    uint32_t a;
    asm("{ .reg .u64 t; cvta.to.shared.u64 t, %1; cvt.u32.u64 %0, t; }" : "=r"(a) : "l"(p));
    return a;
}
__device__ __forceinline__ void cpasync16(uint32_t dst, const void* src) {
    asm volatile("{ .reg .u64 g; cvta.to.global.u64 g, %1; "
                 "cp.async.ca.shared.global [%0], [g], 16; }"
                 :: "r"(dst), "l"(src) : "memory");
}
__device__ __forceinline__ void cpasync_wait() {
    asm volatile("cp.async.commit_group;\n\tcp.async.wait_group 0;" ::: "memory");
}
__device__ __forceinline__ void ldmx4(uint32_t* r, uint32_t addr) {
    asm volatile("ldmatrix.sync.aligned.m8n8.x4.shared.b16 {%0,%1,%2,%3}, [%4];"
                 : "=r"(r[0]), "=r"(r[1]), "=r"(r[2]), "=r"(r[3]) : "r"(addr));
}
__device__ __forceinline__ void mma16816(float* d, const uint32_t* a,
                                         uint32_t b0, uint32_t b1) {
    asm volatile(
        "mma.sync.aligned.m16n8k16.row.col.f32.bf16.bf16.f32 "
        "{%0,%1,%2,%3}, {%4,%5,%6,%7}, {%8,%9}, {%0,%1,%2,%3};"
        : "+f"(d[0]), "+f"(d[1]), "+f"(d[2]), "+f"(d[3])
        : "r"(a[0]), "r"(a[1]), "r"(a[2]), "r"(a[3]), "r"(b0), "r"(b1));
}
__device__ __forceinline__ uint32_t pack_bf16x2(float a, float b) {
    __nv_bfloat162 t = __floats2bfloat162_rn(a, b);
    return *reinterpret_cast<uint32_t*>(&t);
}

// ---------------- Kernel 1: prep (weights + C only) ----------------
__global__ void __launch_bounds__(320) prep_kernel(
    const float* __restrict__ k, const float* __restrict__ bias,
    const float* __restrict__ dxp, const float* __restrict__ dwp)
{
    __shared__ float pe[320], pk[320];
    const int tid = threadIdx.x;
    const int co  = blockIdx.x;              // 64 blocks
    __nv_bfloat16* w2 = reinterpret_cast<__nv_bfloat16*>(g_w4);
    float e = 0.f, kv = 0.f;
    if (tid < 288) {
        kv = k[tid * 64 + co];
        e  = __expf(kv + 5.0f);
        w2[co * 320 + tid] = __float2bfloat16(e - dwp[0]);
    } else {
        w2[co * 320 + tid] = __float2bfloat16(0.f);
    }
    pe[tid] = e; pk[tid] = kv;
    __syncthreads();
    for (int s = 160; s >= 5; s >>= 1) {
        if (tid < s) { pe[tid] += pe[tid + s]; pk[tid] += pk[tid + s]; }
        __syncthreads();
    }
    if (tid == 0) {
        float SE = pe[0] + pe[1] + pe[2] + pe[3] + pe[4];
        float SK = pk[0] + pk[1] + pk[2] + pk[3] + pk[4];
        g_C[co] = SE - dxp[0] * SK + bias[co];
    }
}

// ---------------- Kernel 2: implicit-GEMM conv via HMMA ----------------
constexpr int STRB  = 592;                 // 37*16B rows: conflict-free ldmatrix
constexpr int OFF_A = 0;                   // 64*592 = 37888 ; sD aliases this later
constexpr int OFF_B = 37888;               // 64*592
constexpr int OFF_C = 75776;               // 64 floats
constexpr int SMEMB = OFF_C + 256;
constexpr int CNT   = 512;                 // 16 warps

__global__ void __launch_bounds__(CNT) conv_mma_kernel(
    const float* __restrict__ x, float* __restrict__ out)
{
    extern __shared__ __align__(16) char sm[];
    const uint32_t smb = smem_u32(sm);
    const int tid  = threadIdx.x;
    const int wid  = tid >> 5;
    const int lane = tid & 31;
    const int t    = blockIdx.x;             // M-tile, 98 tiles of 64 rows

    // ---- stage A locally from fp32 x (inline bf16 convert) — overlaps prep ----
    {
        const int row   = tid >> 3;          // 0..63
        const int lane8 = tid & 7;
        int m = t * 64 + row;
        int b = m / 784, rem = m - b * 784;
        int h = rem / 28, w = rem - h * 28;
        const float* xb = x + (size_t)b * 32 * 784;
        char* dA = sm + OFF_A + row * STRB;
        #pragma unroll
        for (int i = 0; i < 5; i++) {
            int c36 = lane8 + 8 * i;
            if (c36 < 36) {
                int seg = c36 >> 2, c8 = c36 & 3;          // 8 cins per 16B chunk
                int kh = seg / 3, kw = seg - kh * 3;
                int ir = h + kh - 1, ic = w + kw - 1;
                uint4 v = make_uint4(0, 0, 0, 0);
                if ((unsigned)ir < 28u && (unsigned)ic < 28u) {
                    const float* p = xb + (size_t)(c8 * 8) * 784 + ir * 28 + ic;
                    v.x = pack_bf16x2(p[0 * 784], p[1 * 784]);
                    v.y = pack_bf16x2(p[2 * 784], p[3 * 784]);
                    v.z = pack_bf16x2(p[4 * 784], p[5 * 784]);
                    v.w = pack_bf16x2(p[6 * 784], p[7 * 784]);
                }
                *reinterpret_cast<uint4*>(dA + c36 * 16) = v;
            }
        }
    }

    // ---- PDL: block until prep grid completes (no-op if not PDL-launched) ----
    asm volatile("griddepcontrol.wait;" ::: "memory");

    // ---- stage B (W''^T) via cp.async; C into smem ----
    float* sC = reinterpret_cast<float*>(sm + OFF_C);
    if (tid < 64) sC[tid] = g_C[tid];
    {
        const int row   = tid >> 3;
        const int lane8 = tid & 7;
        uint32_t dB = smb + OFF_B + row * STRB;
        const uint4* wrow = &g_w4[row * 40];
        #pragma unroll
        for (int i = 0; i < 5; i++) {
            int c = lane8 + 8 * i;
            if (c < 36) cpasync16(dB + c * 16, wrow + c);
        }
    }
    cpasync_wait();
    __syncthreads();

    // ---- 16 warps = 4(M) x 4(N); warp tile 16M x 16N; 2 K-chains ----
    const int wm = (wid & 3) * 16;
    const int wn = (wid >> 2) * 16;
    uint32_t aAddr = smb + OFF_A + (uint32_t)(wm + (lane & 15)) * STRB + (lane >> 4) * 16;
    uint32_t bAddr = smb + OFF_B + (uint32_t)(wn + (lane & 15)) * STRB + (lane >> 4) * 16;

    float acc0[8], acc1[8];
    #pragma unroll
    for (int i = 0; i < 8; i++) { acc0[i] = 0.f; acc1[i] = 0.f; }

    #pragma unroll
    for (int ks = 0; ks < 9; ks++) {
        uint32_t a0[4], b0[4], a1[4], b1[4];
        ldmx4(a0, aAddr + ks * 32);
        ldmx4(b0, bAddr + ks * 32);
        ldmx4(a1, aAddr + (ks + 9) * 32);
        ldmx4(b1, bAddr + (ks + 9) * 32);
        mma16816(acc0 + 0, a0, b0[0], b0[2]);
        mma16816(acc0 + 4, a0, b0[1], b0[3]);
        mma16816(acc1 + 0, a1, b1[0], b1[2]);
        mma16816(acc1 + 4, a1, b1[1], b1[3]);
    }
    #pragma unroll
    for (int i = 0; i < 8; i++) acc0[i] += acc1[i];

    // ---- epilogue: frags -> smem [co][j] (aliases A), coalesced STG ----
    __syncthreads();
    float* sD = reinterpret_cast<float*>(sm + OFF_A);   // stride 65
    {
        const int row  = lane >> 2;
        const int colp = (lane & 3) * 2;
        int j0 = wm + row, j1 = j0 + 8;
        #pragma unroll
        for (int jj = 0; jj < 2; jj++) {
            int co = wn + jj * 8 + colp;
            sD[(co    ) * 65 + j0] = acc0[jj * 4 + 0];
            sD[(co + 1) * 65 + j0] = acc0[jj * 4 + 1];
            sD[(co    ) * 65 + j1] = acc0[jj * 4 + 2];
            sD[(co + 1) * 65 + j1] = acc0[jj * 4 + 3];
        }
    }
    __syncthreads();
    {
        int m0 = t * 64;
        int b0 = m0 / 784;
        int jb = (b0 + 1) * 784 - m0;        // j >= jb -> next batch image
        #pragma unroll
        for (int i = 0; i < 8; i++) {
            int idx = i * CNT + tid;
            int co  = idx >> 6;
            int j   = idx & 63;
            int b   = b0 + (j >= jb ? 1 : 0);
            int hw  = m0 + j - b * 784;
            out[((size_t)(b * 64 + co)) * 784 + hw] = sD[co * 65 + j] + sC[co];
        }
    }
}

// ---------------- launch ----------------
extern "C" void kernel_launch(void* const* d_in, const int* in_sizes, int n_in,
                              void* d_out, int out_size)
{
    (void)in_sizes; (void)n_in; (void)out_size;
    const float* x    = (const float*)d_in[0];
    const float* k    = (const float*)d_in[1];
    const float* bias = (const float*)d_in[2];
    const float* dx   = (const float*)d_in[3];
    const float* dw   = (const float*)d_in[4];
    float* out        = (float*)d_out;

    cudaFuncSetAttribute(conv_mma_kernel,
                         cudaFuncAttributeMaxDynamicSharedMemorySize, SMEMB);

    prep_kernel<<<64, 320>>>(k, bias, dx, dw);

    // conv with Programmatic Dependent Launch: prologue overlaps prep;
    // griddepcontrol.wait inside guards the weight reads.
    cudaLaunchConfig_t cfg = {};
    cfg.gridDim         = dim3(98, 1, 1);
    cfg.blockDim        = dim3(CNT, 1, 1);
    cfg.dynamicSmemBytes = SMEMB;
    cfg.stream          = 0;
    cudaLaunchAttribute attrs[1];
    attrs[0].id = cudaLaunchAttributeProgrammaticStreamSerialization;
    attrs[0].val.programmaticStreamSerializationAllowed = 1;
    cfg.attrs    = attrs;
    cfg.numAttrs = 1;
    cudaLaunchKernelEx(&cfg, conv_mma_kernel, x, out);
}